// round 9
// baseline (speedup 1.0000x reference)
#include <cuda_runtime.h>

// LIF_21260088115614 — fused smooth + GEMM + LIF scan, fp32, FFMA2 GEMM,
// 512-thread CTA (16 warps/SM) for issue-latency hiding.
//
// Bit-identical arithmetic to the round-3/5 passing kernels:
//   - smoothing: same ascending-tap FFMA chain per (t,c) (t-split across threads
//     changes nothing arithmetically)
//   - GEMM: strictly-sequential c=0..255 single-accumulator chains; packed
//     fma.rn.f32x2 lanes are IEEE-rn fp32 FMAs == scalar __fmaf_rn bit-for-bit
//   - LIF scan: same non-contracted __fmul_rn/__fadd_rn sequence
//
// Thread layout (512 threads):
//   GEMM: tr = tid>>6 (0..7) owns a t-chunk (13,13,13,13,12,12,12,12);
//         dg = tid&63 owns d = 4*dg..4*dg+3 (float4 w loads).
//         Every chunk = 6 even-aligned t-pairs (+1 scalar t iff chunk len 13).
//   smoothing: c = tid&255, half = tid>>8 covers t in [50*half, 50*half+50)
//   scan: tid<256, d = tid
//
// inputs: d_in[0] = inputs (2048, 100, 256) f32
//         d_in[1] = w      (256, 256)       f32
//         d_in[2] = epsilon (5,)            f32
// output: d_out = [mem_rec (2048,100,256) | spk_rec (2048,100,256)] f32

#define T_STEPS 100
#define T_PAD   102        // even (b64 align), 102%32=6 -> only 2-way conflicts on smooth writes
#define C_DIM   256
#define SAMPLE_ELEMS (T_STEPS * C_DIM)        // 25600
#define XS_ELEMS     (C_DIM * T_PAD)          // 26112

#define ALPHA_F 0.81873075307798182f
#define BETA_F  0.90483741803595952f

__device__ __forceinline__ unsigned long long pack2(float lo_and_hi)
{
    unsigned long long r;
    asm("mov.b64 %0, {%1, %1};" : "=l"(r) : "f"(lo_and_hi));
    return r;
}

__device__ __forceinline__ void ffma2(unsigned long long& acc,
                                      unsigned long long a,
                                      unsigned long long b)
{
    asm("fma.rn.f32x2 %0, %1, %2, %0;" : "+l"(acc) : "l"(a), "l"(b));
}

__global__ void __launch_bounds__(512, 1)
lif_fused_kernel(const float* __restrict__ in,
                 const float* __restrict__ w,
                 const float* __restrict__ eps,
                 float* __restrict__ out_mem,
                 float* __restrict__ out_spk)
{
    extern __shared__ float smem[];
    float* xs  = smem;             // smoothed, TRANSPOSED [c][T_PAD]
    float* buf = smem + XS_ELEMS;  // raw inputs [t][c], later h1 [t][d]

    const int tid = threadIdx.x;   // 0..511
    const int n   = blockIdx.x;

    // ---- 1. load raw sample into smem (float4, fully coalesced) ----
    {
        const float4* in4  = reinterpret_cast<const float4*>(in + (size_t)n * SAMPLE_ELEMS);
        float4*       buf4 = reinterpret_cast<float4*>(buf);
        #pragma unroll
        for (int i = 0; i < 13; ++i) {
            const int idx = tid + i * 512;
            if (idx < SAMPLE_ELEMS / 4) buf4[idx] = in4[idx];
        }
    }
    const float e0 = eps[0], e1 = eps[1], e2 = eps[2], e3 = eps[3], e4 = eps[4];
    __syncthreads();

    // ---- 2. temporal smoothing: (c, t-half) per thread; write TRANSPOSED xs[c][t] ----
    {
        const int c    = tid & 255;
        const int half = tid >> 8;         // 0 or 1
        const int tbeg = half * 50;
        float* xrow = xs + c * T_PAD;

        float xm2 = half ? buf[(tbeg - 2) * C_DIM + c] : 0.0f;
        float xm1 = half ? buf[(tbeg - 1) * C_DIM + c] : 0.0f;
        float x0  = buf[tbeg * C_DIM + c];
        float xp1 = buf[(tbeg + 1) * C_DIM + c];
        #pragma unroll 5
        for (int tt = 0; tt < 50; ++tt) {
            const int t = tbeg + tt;
            float xp2 = (t + 2 < T_STEPS) ? buf[(t + 2) * C_DIM + c] : 0.0f;
            float s = __fmul_rn(e0, xm2);
            s = __fmaf_rn(e1, xm1, s);
            s = __fmaf_rn(e2, x0,  s);
            s = __fmaf_rn(e3, xp1, s);
            s = __fmaf_rn(e4, xp2, s);
            xrow[t] = s;
            xm2 = xm1; xm1 = x0; x0 = xp1; xp1 = xp2;
        }
    }
    __syncthreads();

    // ---- 3. GEMM h1[t][d] = sum_c xs_t[c][t] * w[c][d], FFMA2 over t-pairs ----
    const int tr = tid >> 6;               // 0..7
    const int dg = tid & 63;
    const int t0 = (tr < 4) ? tr * 13 : 52 + (tr - 4) * 12;
    const bool has_sc = (tr < 4);          // 13-length chunks have one scalar t
    const int odd   = t0 & 1;
    const int pbase = t0 + odd;            // first paired t (even)
    const int sc_t  = odd ? t0 : t0 + 12;  // leftover scalar t (if has_sc)

    unsigned long long acc2[6][4];         // [t-pair][d], lo = earlier t
    float accS[4];
    #pragma unroll
    for (int j = 0; j < 6; ++j)
        #pragma unroll
        for (int d = 0; d < 4; ++d) acc2[j][d] = 0ull;
    accS[0] = accS[1] = accS[2] = accS[3] = 0.0f;

    const float4* w4 = reinterpret_cast<const float4*>(w);   // row c = 64 float4
    float4 wv = __ldg(&w4[dg]);                              // prefetch c=0

    #pragma unroll 2
    for (int c = 0; c < C_DIM; ++c) {
        const float4 wn = __ldg(&w4[((c + 1) & 255) * 64 + dg]);  // prefetch next

        const unsigned long long wx = pack2(wv.x);
        const unsigned long long wy = pack2(wv.y);
        const unsigned long long wz = pack2(wv.z);
        const unsigned long long ww = pack2(wv.w);

        const float* xrow = xs + c * T_PAD;
        const unsigned long long* xp =
            reinterpret_cast<const unsigned long long*>(xrow + pbase);

        #pragma unroll
        for (int j = 0; j < 6; ++j) {
            const unsigned long long x2 = xp[j];   // broadcast LDS.64: (x_t, x_t+1)
            ffma2(acc2[j][0], x2, wx);
            ffma2(acc2[j][1], x2, wy);
            ffma2(acc2[j][2], x2, wz);
            ffma2(acc2[j][3], x2, ww);
        }
        if (has_sc) {                              // warp-uniform branch
            const float xsc = xrow[sc_t];
            accS[0] = __fmaf_rn(xsc, wv.x, accS[0]);
            accS[1] = __fmaf_rn(xsc, wv.y, accS[1]);
            accS[2] = __fmaf_rn(xsc, wv.z, accS[2]);
            accS[3] = __fmaf_rn(xsc, wv.w, accS[3]);
        }
        wv = wn;
    }

    __syncthreads();

    // ---- 4. stage h1 into buf[t][d] ----
    {
        float4* h14 = reinterpret_cast<float4*>(buf);
        #pragma unroll
        for (int j = 0; j < 6; ++j) {
            const int tlo = pbase + 2 * j;
            float2 a0 = *reinterpret_cast<float2*>(&acc2[j][0]);
            float2 a1 = *reinterpret_cast<float2*>(&acc2[j][1]);
            float2 a2 = *reinterpret_cast<float2*>(&acc2[j][2]);
            float2 a3 = *reinterpret_cast<float2*>(&acc2[j][3]);
            h14[tlo * 64 + dg]       = make_float4(a0.x, a1.x, a2.x, a3.x);
            h14[(tlo + 1) * 64 + dg] = make_float4(a0.y, a1.y, a2.y, a3.y);
        }
        if (has_sc)
            h14[sc_t * 64 + dg] = make_float4(accS[0], accS[1], accS[2], accS[3]);
    }
    __syncthreads();

    // ---- 5. LIF scan: thread = output channel d = tid (first 256 threads) ----
    // NON-contracted mul+add, replicating XLA's separate fmul/fadd roundings.
    if (tid < 256) {
        float syn = 0.0f, mem = 0.0f;
        float* om = out_mem + (size_t)n * SAMPLE_ELEMS;
        float* os = out_spk + (size_t)n * SAMPLE_ELEMS;
        #pragma unroll 4
        for (int t = 0; t < T_STEPS; ++t) {
            const float h   = buf[t * C_DIM + tid];
            const float spk = (__fadd_rn(mem, -1.0f) > 0.0f) ? 1.0f : 0.0f;
            om[t * C_DIM + tid] = mem;                      // carry-in mem
            os[t * C_DIM + tid] = spk;
            const float nsyn = __fadd_rn(__fmul_rn(ALPHA_F, syn), h);
            const float bm   = __fadd_rn(__fmul_rn(BETA_F, mem), syn);
            mem = __fmul_rn(bm, __fadd_rn(1.0f, -spk));
            syn = nsyn;
        }
    }
}

extern "C" void kernel_launch(void* const* d_in, const int* in_sizes, int n_in,
                              void* d_out, int out_size)
{
    const float* in  = (const float*)d_in[0];
    const float* w   = (const float*)d_in[1];
    const float* eps = (const float*)d_in[2];
    float* out = (float*)d_out;
    const int half = out_size / 2;   // mem_rec first, then spk_rec

    const int smem_bytes = (XS_ELEMS + SAMPLE_ELEMS) * (int)sizeof(float);  // 206848
    cudaFuncSetAttribute(lif_fused_kernel,
                         cudaFuncAttributeMaxDynamicSharedMemorySize, smem_bytes);

    lif_fused_kernel<<<2048, 512, smem_bytes>>>(in, w, eps, out, out + half);
}

// round 11
// speedup vs baseline: 1.2102x; 1.2102x over previous
#include <cuda_runtime.h>

// LIF_21260088115614 — fused smooth + GEMM + LIF scan, fp32, FFMA2 GEMM.
// 256 threads (round-5 shape), + depth-2 w prefetch, + LDS.128 x-quads.
//
// Bit-identical arithmetic to rounds 3/5:
//   - smoothing: same ascending-tap FFMA chain per (t,c)
//   - GEMM: strictly-sequential c=0..255 single-accumulator chains; packed
//     fma.rn.f32x2 lanes are IEEE-rn fp32 FMAs == scalar __fmaf_rn bit-for-bit
//   - LIF scan: same non-contracted __fmul_rn/__fadd_rn sequence
//
// GEMM thread layout (256 threads): tr = tid>>6 owns t-chunk
//   {0..27, 28..51, 52..75, 76..99} (28,24,24,24 — all quad-aligned);
//   dg = tid&63 owns d = 4*dg..4*dg+3.
//   x fetched as ld.shared.v2.u64 (4 t per LDS), w prefetched 2 c ahead.
//
// inputs: d_in[0] = inputs (2048, 100, 256) f32
//         d_in[1] = w      (256, 256)       f32
//         d_in[2] = epsilon (5,)            f32
// output: d_out = [mem_rec (2048,100,256) | spk_rec (2048,100,256)] f32

#define T_STEPS 100
#define T_PAD   108        // multiple of 4 (16B-aligned quads); gcd(108,32)=4 -> 4-way smooth-store conflicts
#define C_DIM   256
#define SAMPLE_ELEMS (T_STEPS * C_DIM)        // 25600
#define XS_ELEMS     (C_DIM * T_PAD)          // 27648

#define ALPHA_F 0.81873075307798182f
#define BETA_F  0.90483741803595952f

typedef unsigned long long ull;

__device__ __forceinline__ ull pack2(float lo_and_hi)
{
    ull r;
    asm("mov.b64 %0, {%1, %1};" : "=l"(r) : "f"(lo_and_hi));
    return r;
}

__device__ __forceinline__ void ffma2(ull& acc, ull a, ull b)
{
    asm("fma.rn.f32x2 %0, %1, %2, %0;" : "+l"(acc) : "l"(a), "l"(b));
}

__global__ void __launch_bounds__(256, 1)
lif_fused_kernel(const float* __restrict__ in,
                 const float* __restrict__ w,
                 const float* __restrict__ eps,
                 float* __restrict__ out_mem,
                 float* __restrict__ out_spk)
{
    extern __shared__ float smem[];
    float* xs  = smem;             // smoothed, TRANSPOSED [c][T_PAD]
    float* buf = smem + XS_ELEMS;  // raw inputs [t][c], later h1 [t][d]

    const int tid = threadIdx.x;   // 0..255
    const int n   = blockIdx.x;

    // ---- 1. load raw sample into smem (float4, fully coalesced) ----
    {
        const float4* in4  = reinterpret_cast<const float4*>(in + (size_t)n * SAMPLE_ELEMS);
        float4*       buf4 = reinterpret_cast<float4*>(buf);
        #pragma unroll
        for (int i = 0; i < 25; ++i)
            buf4[tid + i * 256] = in4[tid + i * 256];
    }
    const float e0 = eps[0], e1 = eps[1], e2 = eps[2], e3 = eps[3], e4 = eps[4];
    __syncthreads();

    // ---- 2. temporal smoothing: thread = channel c; write TRANSPOSED xs[c][t] ----
    {
        const int c = tid;
        float* xrow = xs + c * T_PAD;
        float xm2 = 0.0f, xm1 = 0.0f;
        float x0  = buf[0 * C_DIM + c];
        float xp1 = buf[1 * C_DIM + c];
        #pragma unroll 4
        for (int t = 0; t < T_STEPS; ++t) {
            float xp2 = (t + 2 < T_STEPS) ? buf[(t + 2) * C_DIM + c] : 0.0f;
            float s = __fmul_rn(e0, xm2);
            s = __fmaf_rn(e1, xm1, s);
            s = __fmaf_rn(e2, x0,  s);
            s = __fmaf_rn(e3, xp1, s);
            s = __fmaf_rn(e4, xp2, s);
            xrow[t] = s;
            xm2 = xm1; xm1 = x0; x0 = xp1; xp1 = xp2;
        }
    }
    __syncthreads();

    // ---- 3. GEMM h1[t][d] = sum_c xs_t[c][t] * w[c][d] ----
    // t-chunks: tr=0 -> [0,28) (7 quads), tr>0 -> 28+(tr-1)*24, 24 t (6 quads)
    const int tr = tid >> 6;
    const int dg = tid & 63;
    const int t0 = (tr == 0) ? 0 : 28 + (tr - 1) * 24;

    ull acc2[14][4];               // [t-pair][d]; tr>0 uses first 12 pairs
    #pragma unroll
    for (int j = 0; j < 14; ++j)
        #pragma unroll
        for (int d = 0; d < 4; ++d) acc2[j][d] = 0ull;

    const float4* w4 = reinterpret_cast<const float4*>(w);   // row c = 64 float4
    float4 wv0 = __ldg(&w4[0 * 64 + dg]);                    // depth-2 prefetch
    float4 wv1 = __ldg(&w4[1 * 64 + dg]);

    #pragma unroll 2
    for (int c = 0; c < C_DIM; ++c) {
        const float4 wn = __ldg(&w4[((c + 2) & 255) * 64 + dg]);

        const ull wx = pack2(wv0.x);
        const ull wy = pack2(wv0.y);
        const ull wz = pack2(wv0.z);
        const ull ww = pack2(wv0.w);

        const ulonglong2* xq =
            reinterpret_cast<const ulonglong2*>(xs + c * T_PAD + t0);

        #pragma unroll
        for (int q = 0; q < 6; ++q) {
            const ulonglong2 x4 = xq[q];   // broadcast LDS.128: t0+4q .. t0+4q+3
            ffma2(acc2[2 * q][0], x4.x, wx);
            ffma2(acc2[2 * q][1], x4.x, wy);
            ffma2(acc2[2 * q][2], x4.x, wz);
            ffma2(acc2[2 * q][3], x4.x, ww);
            ffma2(acc2[2 * q + 1][0], x4.y, wx);
            ffma2(acc2[2 * q + 1][1], x4.y, wy);
            ffma2(acc2[2 * q + 1][2], x4.y, wz);
            ffma2(acc2[2 * q + 1][3], x4.y, ww);
        }
        if (tr == 0) {                     // warp-uniform: 7th quad (t 24..27)
            const ulonglong2 x4 = xq[6];
            ffma2(acc2[12][0], x4.x, wx);
            ffma2(acc2[12][1], x4.x, wy);
            ffma2(acc2[12][2], x4.x, wz);
            ffma2(acc2[12][3], x4.x, ww);
            ffma2(acc2[13][0], x4.y, wx);
            ffma2(acc2[13][1], x4.y, wy);
            ffma2(acc2[13][2], x4.y, wz);
            ffma2(acc2[13][3], x4.y, ww);
        }
        wv0 = wv1; wv1 = wn;
    }

    __syncthreads();

    // ---- 4. stage h1 into buf[t][d] ----
    {
        float4* h14 = reinterpret_cast<float4*>(buf);
        #pragma unroll
        for (int j = 0; j < 12; ++j) {
            const int tlo = t0 + 2 * j;
            float2 a0 = *reinterpret_cast<float2*>(&acc2[j][0]);
            float2 a1 = *reinterpret_cast<float2*>(&acc2[j][1]);
            float2 a2 = *reinterpret_cast<float2*>(&acc2[j][2]);
            float2 a3 = *reinterpret_cast<float2*>(&acc2[j][3]);
            h14[tlo * 64 + dg]       = make_float4(a0.x, a1.x, a2.x, a3.x);
            h14[(tlo + 1) * 64 + dg] = make_float4(a0.y, a1.y, a2.y, a3.y);
        }
        if (tr == 0) {
            #pragma unroll
            for (int j = 12; j < 14; ++j) {
                const int tlo = t0 + 2 * j;
                float2 a0 = *reinterpret_cast<float2*>(&acc2[j][0]);
                float2 a1 = *reinterpret_cast<float2*>(&acc2[j][1]);
                float2 a2 = *reinterpret_cast<float2*>(&acc2[j][2]);
                float2 a3 = *reinterpret_cast<float2*>(&acc2[j][3]);
                h14[tlo * 64 + dg]       = make_float4(a0.x, a1.x, a2.x, a3.x);
                h14[(tlo + 1) * 64 + dg] = make_float4(a0.y, a1.y, a2.y, a3.y);
            }
        }
    }
    __syncthreads();

    // ---- 5. LIF scan: thread = output channel d = tid ----
    // NON-contracted mul+add, replicating XLA's separate fmul/fadd roundings.
    {
        float syn = 0.0f, mem = 0.0f;
        float* om = out_mem + (size_t)n * SAMPLE_ELEMS;
        float* os = out_spk + (size_t)n * SAMPLE_ELEMS;
        #pragma unroll 4
        for (int t = 0; t < T_STEPS; ++t) {
            const float h   = buf[t * C_DIM + tid];
            const float spk = (__fadd_rn(mem, -1.0f) > 0.0f) ? 1.0f : 0.0f;
            om[t * C_DIM + tid] = mem;                      // carry-in mem
            os[t * C_DIM + tid] = spk;
            const float nsyn = __fadd_rn(__fmul_rn(ALPHA_F, syn), h);
            const float bm   = __fadd_rn(__fmul_rn(BETA_F, mem), syn);
            mem = __fmul_rn(bm, __fadd_rn(1.0f, -spk));
            syn = nsyn;
        }
    }
}

extern "C" void kernel_launch(void* const* d_in, const int* in_sizes, int n_in,
                              void* d_out, int out_size)
{
    const float* in  = (const float*)d_in[0];
    const float* w   = (const float*)d_in[1];
    const float* eps = (const float*)d_in[2];
    float* out = (float*)d_out;
    const int half = out_size / 2;   // mem_rec first, then spk_rec

    const int smem_bytes = (XS_ELEMS + SAMPLE_ELEMS) * (int)sizeof(float);  // 212992
    cudaFuncSetAttribute(lif_fused_kernel,
                         cudaFuncAttributeMaxDynamicSharedMemorySize, smem_bytes);

    lif_fused_kernel<<<2048, 256, smem_bytes>>>(in, w, eps, out, out + half);
}